// round 12
// baseline (speedup 1.0000x reference)
#include <cuda_runtime.h>

// InducingLocationsSpatialTransform: bilinear affine warp
// X: (N=512, H=64, W=64, C=32) f32, theta: (N, 6) f32 -> out: (N,H,W,C) f32
//
// R11 persistent structure (8 lanes/pixel float4, 4 px/thread, one-wave
// grid) + clamp-aware predicated gathers: when a coordinate is clamped
// (x0==x1 or y0==y1, ~45% each for N(0,1) theta), the duplicate corner
// loads are skipped (@P LDG) and reconstructed by register copy —
// cutting L1 wavefronts/pixel from 5 to ~3.4 (the binding resource).

#define N_ 512
#define H_ 64
#define W_ 64
#define C_ 32
#define HW_ (H_ * W_)
#define VBLOCKS 8192

__global__ __launch_bounds__(512, 4) void st_kernel(
    const float* __restrict__ X,
    const float* __restrict__ theta,
    float* __restrict__ out)
{
    for (int vb = blockIdx.x; vb < VBLOCKS; vb += gridDim.x) {
        int tid = vb * 512 + threadIdx.x;
        int q   = tid >> 3;        // 4-pixel group id
        int cg  = tid & 7;         // float4 group within the 32 channels

        int pid0 = q << 2;
        int n = pid0 >> 12;
        int p = pid0 & 4095;
        int y = p >> 6;
        int x = p & 63;

        const float* th = theta + n * 6;
        float t0 = __ldg(th + 0), t1 = __ldg(th + 1), t2 = __ldg(th + 2);
        float t3 = __ldg(th + 3), t4 = __ldg(th + 4), t5 = __ldg(th + 5);

        const float step = 2.0f / 63.0f;
        float xt = -1.0f + (float)x * step;
        float yt = -1.0f + (float)y * step;

        float gx0 = (float)W_ * ((t0 * xt + t1 * yt + t2) + 1.0f) * 0.5f;
        float gy0 = (float)H_ * ((t3 * xt + t4 * yt + t5) + 1.0f) * 0.5f;
        float dgx = (0.5f * (float)W_ * step) * t0;
        float dgy = (0.5f * (float)H_ * step) * t3;

        const float4* S = (const float4*)(X + (size_t)n * (HW_ * C_));
        float4* O = (float4*)out + (size_t)pid0 * 8;

        #pragma unroll
        for (int k = 0; k < 4; k += 2) {
            float gxa = gx0 + (float)k * dgx;
            float gya = gy0 + (float)k * dgy;
            float gxb = gxa + dgx;
            float gyb = gya + dgy;

            float fxa = floorf(gxa), fya = floorf(gya);
            float fxb = floorf(gxb), fyb = floorf(gyb);
            int ax0 = min(max((int)fxa,     0), W_ - 1);
            int ax1 = min(max((int)fxa + 1, 0), W_ - 1);
            int ay0 = min(max((int)fya,     0), H_ - 1);
            int ay1 = min(max((int)fya + 1, 0), H_ - 1);
            int bx0 = min(max((int)fxb,     0), W_ - 1);
            int bx1 = min(max((int)fxb + 1, 0), W_ - 1);
            int by0 = min(max((int)fyb,     0), H_ - 1);
            int by1 = min(max((int)fyb + 1, 0), H_ - 1);

            bool dXa = (ax1 != ax0), dYa = (ay1 != ay0);
            bool dXb = (bx1 != bx0), dYb = (by1 != by0);

            // pixel a: base corner always loaded; duplicates elided.
            float4 va0 = __ldg(&S[(ay0 * W_ + ax0) * 8 + cg]);
            float4 vb0 = va0;
            if (dYa) vb0 = __ldg(&S[(ay1 * W_ + ax0) * 8 + cg]);
            float4 vc0 = va0;
            if (dXa) vc0 = __ldg(&S[(ay0 * W_ + ax1) * 8 + cg]);
            float4 vd0 = dXa ? vc0 : vb0;        // correct unless dXa&&dYa
            if (dXa && dYa) vd0 = __ldg(&S[(ay1 * W_ + ax1) * 8 + cg]);

            // pixel b
            float4 va1 = __ldg(&S[(by0 * W_ + bx0) * 8 + cg]);
            float4 vb1 = va1;
            if (dYb) vb1 = __ldg(&S[(by1 * W_ + bx0) * 8 + cg]);
            float4 vc1 = va1;
            if (dXb) vc1 = __ldg(&S[(by0 * W_ + bx1) * 8 + cg]);
            float4 vd1 = dXb ? vc1 : vb1;
            if (dXb && dYb) vd1 = __ldg(&S[(by1 * W_ + bx1) * 8 + cg]);

            // weights from clipped corners (identical arithmetic to ref)
            float wa0 = ((float)ax1 - gxa) * ((float)ay1 - gya);
            float wb0 = ((float)ax1 - gxa) * (gya - (float)ay0);
            float wc0 = (gxa - (float)ax0) * ((float)ay1 - gya);
            float wd0 = (gxa - (float)ax0) * (gya - (float)ay0);
            float wa1 = ((float)bx1 - gxb) * ((float)by1 - gyb);
            float wb1 = ((float)bx1 - gxb) * (gyb - (float)by0);
            float wc1 = (gxb - (float)bx0) * ((float)by1 - gyb);
            float wd1 = (gxb - (float)bx0) * (gyb - (float)by0);

            float4 r0, r1;
            r0.x = wa0 * va0.x + wb0 * vb0.x + wc0 * vc0.x + wd0 * vd0.x;
            r0.y = wa0 * va0.y + wb0 * vb0.y + wc0 * vc0.y + wd0 * vd0.y;
            r0.z = wa0 * va0.z + wb0 * vb0.z + wc0 * vc0.z + wd0 * vd0.z;
            r0.w = wa0 * va0.w + wb0 * vb0.w + wc0 * vc0.w + wd0 * vd0.w;
            r1.x = wa1 * va1.x + wb1 * vb1.x + wc1 * vc1.x + wd1 * vd1.x;
            r1.y = wa1 * va1.y + wb1 * vb1.y + wc1 * vc1.y + wd1 * vd1.y;
            r1.z = wa1 * va1.z + wb1 * vb1.z + wc1 * vc1.z + wd1 * vd1.z;
            r1.w = wa1 * va1.w + wb1 * vb1.w + wc1 * vc1.w + wd1 * vd1.w;

            O[k * 8 + cg]       = r0;
            O[(k + 1) * 8 + cg] = r1;
        }
    }
}

extern "C" void kernel_launch(void* const* d_in, const int* in_sizes, int n_in,
                              void* d_out, int out_size)
{
    const float* X     = (const float*)d_in[0];
    const float* theta = (const float*)d_in[1];
    float* out         = (float*)d_out;

    st_kernel<<<592, 512>>>(X, theta, out);   // one wave: 148 SMs x 4 CTAs
}

// round 13
// speedup vs baseline: 2.9817x; 2.9817x over previous
#include <cuda_runtime.h>

// InducingLocationsSpatialTransform: bilinear affine warp
// X: (N=512, H=64, W=64, C=32) f32, theta: (N, 6) f32 -> out: (N,H,W,C) f32
//
// R11 structure (8 lanes/pixel float4 gathers, 4 px/thread, 512-thread CTAs)
// + warp-uniform zero shortcut: reference weights from clipped corners cancel
// EXACTLY to 0 whenever floor(gx) not in [0,62] or floor(gy) not in [0,62]
// (clamped corner pair -> equal values, exactly-negated weights). If ALL
// pixels of the warp's k-pair are out of range (warp vote -> uniform branch,
// no divergence), store zeros and skip all 8 gathers + weight math.

#define N_ 512
#define H_ 64
#define W_ 64
#define C_ 32
#define HW_ (H_ * W_)

__global__ __launch_bounds__(512, 4) void st_kernel(
    const float* __restrict__ X,
    const float* __restrict__ theta,
    float* __restrict__ out)
{
    int tid = blockIdx.x * 512 + threadIdx.x;
    int q   = tid >> 3;        // 4-pixel group id
    int cg  = tid & 7;         // float4 group within the 32 channels

    int pid0 = q << 2;
    int n = pid0 >> 12;
    int p = pid0 & 4095;
    int y = p >> 6;
    int x = p & 63;

    const float* th = theta + n * 6;
    float t0 = __ldg(th + 0), t1 = __ldg(th + 1), t2 = __ldg(th + 2);
    float t3 = __ldg(th + 3), t4 = __ldg(th + 4), t5 = __ldg(th + 5);

    const float step = 2.0f / 63.0f;
    float xt = -1.0f + (float)x * step;
    float yt = -1.0f + (float)y * step;

    float gx0 = (float)W_ * ((t0 * xt + t1 * yt + t2) + 1.0f) * 0.5f;
    float gy0 = (float)H_ * ((t3 * xt + t4 * yt + t5) + 1.0f) * 0.5f;
    float dgx = (0.5f * (float)W_ * step) * t0;
    float dgy = (0.5f * (float)H_ * step) * t3;

    const float4* S = (const float4*)(X + (size_t)n * (HW_ * C_));
    float4* O = (float4*)out + (size_t)pid0 * 8;

    const float4 zero4 = make_float4(0.f, 0.f, 0.f, 0.f);

    #pragma unroll
    for (int k = 0; k < 4; k += 2) {
        float gxa = gx0 + (float)k * dgx;
        float gya = gy0 + (float)k * dgy;
        float gxb = gxa + dgx;
        float gyb = gya + dgy;

        float fxa = floorf(gxa), fya = floorf(gya);
        float fxb = floorf(gxb), fyb = floorf(gyb);

        // In-range <=> floor coords in [0, 62] for both axes.
        bool inA = (fxa >= 0.f) & (fxa <= 62.f) & (fya >= 0.f) & (fya <= 62.f);
        bool inB = (fxb >= 0.f) & (fxb <= 62.f) & (fyb >= 0.f) & (fyb <= 62.f);

        // Warp-uniform vote: if EVERY pixel in this warp's k-pair is out of
        // range, the outputs are exact zeros -> skip gathers entirely.
        if (!__any_sync(0xffffffffu, inA | inB)) {
            O[k * 8 + cg]       = zero4;
            O[(k + 1) * 8 + cg] = zero4;
            continue;
        }

        // Full path (identical to R11): clamped corners; out-of-range
        // pixels inside an in-warp cancel to exact zeros by construction.
        int ax0 = min(max((int)fxa,     0), W_ - 1);
        int ax1 = min(max((int)fxa + 1, 0), W_ - 1);
        int ay0 = min(max((int)fya,     0), H_ - 1);
        int ay1 = min(max((int)fya + 1, 0), H_ - 1);
        int bx0 = min(max((int)fxb,     0), W_ - 1);
        int bx1 = min(max((int)fxb + 1, 0), W_ - 1);
        int by0 = min(max((int)fyb,     0), H_ - 1);
        int by1 = min(max((int)fyb + 1, 0), H_ - 1);

        float4 va0 = __ldg(&S[(ay0 * W_ + ax0) * 8 + cg]);
        float4 vb0 = __ldg(&S[(ay1 * W_ + ax0) * 8 + cg]);
        float4 vc0 = __ldg(&S[(ay0 * W_ + ax1) * 8 + cg]);
        float4 vd0 = __ldg(&S[(ay1 * W_ + ax1) * 8 + cg]);
        float4 va1 = __ldg(&S[(by0 * W_ + bx0) * 8 + cg]);
        float4 vb1 = __ldg(&S[(by1 * W_ + bx0) * 8 + cg]);
        float4 vc1 = __ldg(&S[(by0 * W_ + bx1) * 8 + cg]);
        float4 vd1 = __ldg(&S[(by1 * W_ + bx1) * 8 + cg]);

        float wa0 = ((float)ax1 - gxa) * ((float)ay1 - gya);
        float wb0 = ((float)ax1 - gxa) * (gya - (float)ay0);
        float wc0 = (gxa - (float)ax0) * ((float)ay1 - gya);
        float wd0 = (gxa - (float)ax0) * (gya - (float)ay0);
        float wa1 = ((float)bx1 - gxb) * ((float)by1 - gyb);
        float wb1 = ((float)bx1 - gxb) * (gyb - (float)by0);
        float wc1 = (gxb - (float)bx0) * ((float)by1 - gyb);
        float wd1 = (gxb - (float)bx0) * (gyb - (float)by0);

        float4 r0, r1;
        r0.x = wa0 * va0.x + wb0 * vb0.x + wc0 * vc0.x + wd0 * vd0.x;
        r0.y = wa0 * va0.y + wb0 * vb0.y + wc0 * vc0.y + wd0 * vd0.y;
        r0.z = wa0 * va0.z + wb0 * vb0.z + wc0 * vc0.z + wd0 * vd0.z;
        r0.w = wa0 * va0.w + wb0 * vb0.w + wc0 * vc0.w + wd0 * vd0.w;
        r1.x = wa1 * va1.x + wb1 * vb1.x + wc1 * vc1.x + wd1 * vd1.x;
        r1.y = wa1 * va1.y + wb1 * vb1.y + wc1 * vc1.y + wd1 * vd1.y;
        r1.z = wa1 * va1.z + wb1 * vb1.z + wc1 * vc1.z + wd1 * vd1.z;
        r1.w = wa1 * va1.w + wb1 * vb1.w + wc1 * vc1.w + wd1 * vd1.w;

        O[k * 8 + cg]       = r0;
        O[(k + 1) * 8 + cg] = r1;
    }
}

extern "C" void kernel_launch(void* const* d_in, const int* in_sizes, int n_in,
                              void* d_out, int out_size)
{
    const float* X     = (const float*)d_in[0];
    const float* theta = (const float*)d_in[1];
    float* out         = (float*)d_out;

    int threads = 512;
    int blocks = (N_ * HW_ * 2) / threads;   // 8192
    st_kernel<<<blocks, threads>>>(X, theta, out);
}

// round 14
// speedup vs baseline: 3.1284x; 1.0492x over previous
#include <cuda_runtime.h>

// InducingLocationsSpatialTransform: bilinear affine warp
// X: (N=512, H=64, W=64, C=32) f32, theta: (N, 6) f32 -> out: (N,H,W,C) f32
//
// R13 + per-pixel warp-uniform zero votes (split a/b: a boundary pair no
// longer forces gathers for its exact-zero member) + streaming stores
// (__stcs, evict-first: keeps L2 for the gather-read working set).
// Zero shortcut validity: with clipped corners, out-of-range floor(gx) or
// floor(gy) collapses a corner pair to identical values with exactly
// negated weights -> output is exactly 0.0f.

#define N_ 512
#define H_ 64
#define W_ 64
#define C_ 32
#define HW_ (H_ * W_)

__global__ __launch_bounds__(512, 4) void st_kernel(
    const float* __restrict__ X,
    const float* __restrict__ theta,
    float* __restrict__ out)
{
    const unsigned FULL = 0xffffffffu;
    int tid = blockIdx.x * 512 + threadIdx.x;
    int q   = tid >> 3;        // 4-pixel group id
    int cg  = tid & 7;         // float4 group within the 32 channels

    int pid0 = q << 2;
    int n = pid0 >> 12;
    int p = pid0 & 4095;
    int y = p >> 6;
    int x = p & 63;

    const float* th = theta + n * 6;
    float t0 = __ldg(th + 0), t1 = __ldg(th + 1), t2 = __ldg(th + 2);
    float t3 = __ldg(th + 3), t4 = __ldg(th + 4), t5 = __ldg(th + 5);

    const float step = 2.0f / 63.0f;
    float xt = -1.0f + (float)x * step;
    float yt = -1.0f + (float)y * step;

    float gx0 = (float)W_ * ((t0 * xt + t1 * yt + t2) + 1.0f) * 0.5f;
    float gy0 = (float)H_ * ((t3 * xt + t4 * yt + t5) + 1.0f) * 0.5f;
    float dgx = (0.5f * (float)W_ * step) * t0;
    float dgy = (0.5f * (float)H_ * step) * t3;

    const float4* S = (const float4*)(X + (size_t)n * (HW_ * C_));
    float4* O = (float4*)out + (size_t)pid0 * 8;

    const float4 zero4 = make_float4(0.f, 0.f, 0.f, 0.f);

    #pragma unroll
    for (int k = 0; k < 4; k += 2) {
        float gxa = gx0 + (float)k * dgx;
        float gya = gy0 + (float)k * dgy;
        float gxb = gxa + dgx;
        float gyb = gya + dgy;

        float fxa = floorf(gxa), fya = floorf(gya);
        float fxb = floorf(gxb), fyb = floorf(gyb);

        bool inA = (fxa >= 0.f) & (fxa <= 62.f) & (fya >= 0.f) & (fya <= 62.f);
        bool inB = (fxb >= 0.f) & (fxb <= 62.f) & (fyb >= 0.f) & (fyb <= 62.f);

        bool anyA = __any_sync(FULL, inA);
        bool anyB = __any_sync(FULL, inB);

        // ---- pixel a ----
        if (anyA) {
            int ax0 = min(max((int)fxa,     0), W_ - 1);
            int ax1 = min(max((int)fxa + 1, 0), W_ - 1);
            int ay0 = min(max((int)fya,     0), H_ - 1);
            int ay1 = min(max((int)fya + 1, 0), H_ - 1);

            float4 va = __ldg(&S[(ay0 * W_ + ax0) * 8 + cg]);
            float4 vb = __ldg(&S[(ay1 * W_ + ax0) * 8 + cg]);
            float4 vc = __ldg(&S[(ay0 * W_ + ax1) * 8 + cg]);
            float4 vd = __ldg(&S[(ay1 * W_ + ax1) * 8 + cg]);

            float wa = ((float)ax1 - gxa) * ((float)ay1 - gya);
            float wb = ((float)ax1 - gxa) * (gya - (float)ay0);
            float wc = (gxa - (float)ax0) * ((float)ay1 - gya);
            float wd = (gxa - (float)ax0) * (gya - (float)ay0);

            float4 r;
            r.x = wa * va.x + wb * vb.x + wc * vc.x + wd * vd.x;
            r.y = wa * va.y + wb * vb.y + wc * vc.y + wd * vd.y;
            r.z = wa * va.z + wb * vb.z + wc * vc.z + wd * vd.z;
            r.w = wa * va.w + wb * vb.w + wc * vc.w + wd * vd.w;
            __stcs(&O[k * 8 + cg], r);
        } else {
            __stcs(&O[k * 8 + cg], zero4);
        }

        // ---- pixel b ----
        if (anyB) {
            int bx0 = min(max((int)fxb,     0), W_ - 1);
            int bx1 = min(max((int)fxb + 1, 0), W_ - 1);
            int by0 = min(max((int)fyb,     0), H_ - 1);
            int by1 = min(max((int)fyb + 1, 0), H_ - 1);

            float4 va = __ldg(&S[(by0 * W_ + bx0) * 8 + cg]);
            float4 vb = __ldg(&S[(by1 * W_ + bx0) * 8 + cg]);
            float4 vc = __ldg(&S[(by0 * W_ + bx1) * 8 + cg]);
            float4 vd = __ldg(&S[(by1 * W_ + bx1) * 8 + cg]);

            float wa = ((float)bx1 - gxb) * ((float)by1 - gyb);
            float wb = ((float)bx1 - gxb) * (gyb - (float)by0);
            float wc = (gxb - (float)bx0) * ((float)by1 - gyb);
            float wd = (gxb - (float)bx0) * (gyb - (float)by0);

            float4 r;
            r.x = wa * va.x + wb * vb.x + wc * vc.x + wd * vd.x;
            r.y = wa * va.y + wb * vb.y + wc * vc.y + wd * vd.y;
            r.z = wa * va.z + wb * vb.z + wc * vc.z + wd * vd.z;
            r.w = wa * va.w + wb * vb.w + wc * vc.w + wd * vd.w;
            __stcs(&O[(k + 1) * 8 + cg], r);
        } else {
            __stcs(&O[(k + 1) * 8 + cg], zero4);
        }
    }
}

extern "C" void kernel_launch(void* const* d_in, const int* in_sizes, int n_in,
                              void* d_out, int out_size)
{
    const float* X     = (const float*)d_in[0];
    const float* theta = (const float*)d_in[1];
    float* out         = (float*)d_out;

    int threads = 512;
    int blocks = (N_ * HW_ * 2) / threads;   // 8192
    st_kernel<<<blocks, threads>>>(X, theta, out);
}